// round 1
// baseline (speedup 1.0000x reference)
#include <cuda_runtime.h>
#include <math.h>

// Problem constants
#define NROWS 8192      // 2B rows
#define HALF  4096
#define DIM   2048      // embed dim
#define PD    256       // projection dim
#define NT    64        // 8192/128 tiles per dim

// Scratch (device globals; no allocation allowed)
__device__ float g_norm[NROWS * PD];       // out_head, then normalized in place (8 MB)
__device__ float g_part[NT * NROWS];       // per-tile partial neg sums (2 MB)
__device__ float g_neg[NROWS];
__device__ float g_pos[HALF];

// ---------------------------------------------------------------------------
// K1: C[8192,256] = A[8192,2048] @ W[2048,256] + b   (fp32 tiled GEMM)
// BM=128, BN=64, BK=16, 256 threads, 8x4 microtile
// ---------------------------------------------------------------------------
__global__ void __launch_bounds__(256) k_gemm1(
    const float* __restrict__ A, const float* __restrict__ W,
    const float* __restrict__ b, float* __restrict__ C)
{
    __shared__ float As[16][128 + 4];
    __shared__ float Ws[16][64];

    const int bx = blockIdx.x;           // 0..63 (row tiles)
    const int by = blockIdx.y;           // 0..3  (col tiles)
    const int tid = threadIdx.x;
    const int tx = tid & 15, ty = tid >> 4;
    const int row0 = bx * 128, col0 = by * 64;

    float acc[8][4];
    #pragma unroll
    for (int i = 0; i < 8; i++)
        #pragma unroll
        for (int j = 0; j < 4; j++) acc[i][j] = 0.f;

    for (int kk = 0; kk < DIM; kk += 16) {
        // A tile: 128x16 = 512 float4, 2 per thread (store transposed k-major)
        #pragma unroll
        for (int i = 0; i < 2; i++) {
            int idx = tid + i * 256;
            int r = idx >> 2, q = idx & 3;
            float4 v = *(const float4*)&A[(size_t)(row0 + r) * DIM + kk + q * 4];
            As[q * 4 + 0][r] = v.x; As[q * 4 + 1][r] = v.y;
            As[q * 4 + 2][r] = v.z; As[q * 4 + 3][r] = v.w;
        }
        // W tile: 16x64 = 256 float4, 1 per thread
        {
            int r = tid >> 4, q = tid & 15;
            float4 v = *(const float4*)&W[(size_t)(kk + r) * PD + col0 + q * 4];
            *(float4*)&Ws[r][q * 4] = v;
        }
        __syncthreads();
        #pragma unroll
        for (int k = 0; k < 16; k++) {
            float a[8], w[4];
            #pragma unroll
            for (int i = 0; i < 8; i++) a[i] = As[k][ty * 8 + i];
            #pragma unroll
            for (int j = 0; j < 4; j++) w[j] = Ws[k][tx * 4 + j];
            #pragma unroll
            for (int i = 0; i < 8; i++)
                #pragma unroll
                for (int j = 0; j < 4; j++) acc[i][j] += a[i] * w[j];
        }
        __syncthreads();
    }
    #pragma unroll
    for (int i = 0; i < 8; i++)
        #pragma unroll
        for (int j = 0; j < 4; j++) {
            int r = row0 + ty * 8 + i, c = col0 + tx * 4 + j;
            C[(size_t)r * PD + c] = acc[i][j] + b[c];
        }
}

// ---------------------------------------------------------------------------
// K2: row L2-normalize in place (x / max(||x||, 1e-12)). One block per row.
// ---------------------------------------------------------------------------
__global__ void __launch_bounds__(256) k_norm(float* __restrict__ X)
{
    __shared__ float sh[256];
    float* x = X + (size_t)blockIdx.x * PD;
    float v = x[threadIdx.x];
    sh[threadIdx.x] = v * v;
    __syncthreads();
    #pragma unroll
    for (int o = 128; o > 0; o >>= 1) {
        if (threadIdx.x < o) sh[threadIdx.x] += sh[threadIdx.x + o];
        __syncthreads();
    }
    float inv = 1.0f / fmaxf(sqrtf(sh[0]), 1e-12f);
    x[threadIdx.x] = v * inv;
}

// ---------------------------------------------------------------------------
// K3: pos dots d_i = n_i . n_{i+4096}   (warp per i)
// ---------------------------------------------------------------------------
__global__ void __launch_bounds__(256) k_pos(const float* __restrict__ Nm,
                                             float* __restrict__ pos)
{
    int w = (blockIdx.x * blockDim.x + threadIdx.x) >> 5;
    int lane = threadIdx.x & 31;
    if (w >= HALF) return;
    const float* a = Nm + (size_t)w * PD;
    const float* c = Nm + (size_t)(w + HALF) * PD;
    float s = 0.f;
    #pragma unroll
    for (int k = lane; k < PD; k += 32) s += a[k] * c[k];
    #pragma unroll
    for (int o = 16; o > 0; o >>= 1) s += __shfl_down_sync(0xffffffff, s, o);
    if (lane == 0) pos[w] = s;
}

// ---------------------------------------------------------------------------
// K4: symmetric sim tiles. Block handles tile (bi,bj), bi<=bj, 128x128x256.
// Epilogue: exp(10*sim) with diagonal masked, per-tile row-sums -> g_part[bj],
// col-sums -> g_part[bi]. Each (slot,row) has exactly one writer => deterministic.
// ---------------------------------------------------------------------------
__global__ void __launch_bounds__(256) k_sim(const float* __restrict__ Nm,
                                             float* __restrict__ part)
{
    // linear block -> (bi,bj) upper triangle incl diagonal
    int L = blockIdx.x;
    int bi = 0, rem = L;
    while (rem >= NT - bi) { rem -= NT - bi; bi++; }
    int bj = bi + rem;

    __shared__ float As[32][128 + 4];
    __shared__ float Bs[32][128 + 4];
    __shared__ float red[128][17];

    const int tid = threadIdx.x;
    const int tx = tid & 15, ty = tid >> 4;
    const int ro = bi * 128, co = bj * 128;

    float acc[8][8];
    #pragma unroll
    for (int i = 0; i < 8; i++)
        #pragma unroll
        for (int j = 0; j < 8; j++) acc[i][j] = 0.f;

    for (int kk = 0; kk < PD; kk += 32) {
        #pragma unroll
        for (int i = 0; i < 4; i++) {
            int idx = tid + i * 256;
            int r = idx >> 3, q = idx & 7;
            float4 v = *(const float4*)&Nm[(size_t)(ro + r) * PD + kk + q * 4];
            As[q * 4 + 0][r] = v.x; As[q * 4 + 1][r] = v.y;
            As[q * 4 + 2][r] = v.z; As[q * 4 + 3][r] = v.w;
            float4 u = *(const float4*)&Nm[(size_t)(co + r) * PD + kk + q * 4];
            Bs[q * 4 + 0][r] = u.x; Bs[q * 4 + 1][r] = u.y;
            Bs[q * 4 + 2][r] = u.z; Bs[q * 4 + 3][r] = u.w;
        }
        __syncthreads();
        #pragma unroll
        for (int k = 0; k < 32; k++) {
            float a[8], bv[8];
            #pragma unroll
            for (int i = 0; i < 8; i++) a[i] = As[k][ty * 8 + i];
            #pragma unroll
            for (int j = 0; j < 8; j++) bv[j] = Bs[k][tx * 8 + j];
            #pragma unroll
            for (int i = 0; i < 8; i++)
                #pragma unroll
                for (int j = 0; j < 8; j++) acc[i][j] += a[i] * bv[j];
        }
        __syncthreads();
    }

    // epilogue: exp + mask + per-thread row/col partials
    float rs[8], cs[8];
    #pragma unroll
    for (int i = 0; i < 8; i++) { rs[i] = 0.f; cs[i] = 0.f; }
    #pragma unroll
    for (int i = 0; i < 8; i++) {
        int gi = ro + ty * 8 + i;
        #pragma unroll
        for (int j = 0; j < 8; j++) {
            int gj = co + tx * 8 + j;
            float v = (gi == gj) ? 0.0f : __expf(acc[i][j] * 10.0f);
            rs[i] += v;
            cs[j] += v;
        }
    }

    // reduce row sums across the 16 thread-columns
    #pragma unroll
    for (int i = 0; i < 8; i++) red[ty * 8 + i][tx] = rs[i];
    __syncthreads();
    if (tid < 128) {
        float s = 0.f;
        #pragma unroll
        for (int t = 0; t < 16; t++) s += red[tid][t];
        part[(size_t)bj * NROWS + ro + tid] = s;
    }
    __syncthreads();

    if (bi != bj) {
        // reduce col sums across the 16 thread-rows
        #pragma unroll
        for (int j = 0; j < 8; j++) red[tx * 8 + j][ty] = cs[j];
        __syncthreads();
        if (tid < 128) {
            float s = 0.f;
            #pragma unroll
            for (int t = 0; t < 16; t++) s += red[tid][t];
            part[(size_t)bi * NROWS + co + tid] = s;
        }
    }
}

// ---------------------------------------------------------------------------
// K5: neg[i] = sum over 64 slots (fixed order => deterministic)
// ---------------------------------------------------------------------------
__global__ void __launch_bounds__(256) k_neg(const float* __restrict__ part,
                                             float* __restrict__ neg)
{
    int i = blockIdx.x * blockDim.x + threadIdx.x;
    float s = 0.f;
    #pragma unroll
    for (int t = 0; t < NT; t++) s += part[(size_t)t * NROWS + i];
    neg[i] = s;
}

// ---------------------------------------------------------------------------
// K6: loss = (sum log(neg) - 20 * sum pos_d) / 8192
// ---------------------------------------------------------------------------
__global__ void __launch_bounds__(256) k_loss(const float* __restrict__ neg,
                                              const float* __restrict__ pos,
                                              float* __restrict__ out)
{
    __shared__ float sh[256];
    float s = 0.f;
    for (int i = threadIdx.x; i < NROWS; i += 256) s += logf(neg[i]);
    float p = 0.f;
    for (int i = threadIdx.x; i < HALF; i += 256) p += pos[i];

    sh[threadIdx.x] = s;
    __syncthreads();
    #pragma unroll
    for (int o = 128; o > 0; o >>= 1) {
        if (threadIdx.x < o) sh[threadIdx.x] += sh[threadIdx.x + o];
        __syncthreads();
    }
    float sumlog = sh[0];
    __syncthreads();
    sh[threadIdx.x] = p;
    __syncthreads();
    #pragma unroll
    for (int o = 128; o > 0; o >>= 1) {
        if (threadIdx.x < o) sh[threadIdx.x] += sh[threadIdx.x + o];
        __syncthreads();
    }
    if (threadIdx.x == 0)
        out[0] = (sumlog - 20.0f * sh[0]) / (float)NROWS;
}

// ---------------------------------------------------------------------------
extern "C" void kernel_launch(void* const* d_in, const int* in_sizes, int n_in,
                              void* d_out, int out_size)
{
    const float* X = (const float*)d_in[0];  // [8192, 2048]
    const float* W = (const float*)d_in[1];  // [2048, 256]
    const float* b = (const float*)d_in[2];  // [256]
    float* out = (float*)d_out;

    float* nrm;  cudaGetSymbolAddress((void**)&nrm,  g_norm);
    float* part; cudaGetSymbolAddress((void**)&part, g_part);
    float* neg;  cudaGetSymbolAddress((void**)&neg,  g_neg);
    float* pos;  cudaGetSymbolAddress((void**)&pos,  g_pos);

    k_gemm1<<<dim3(64, 4), 256>>>(X, W, b, nrm);
    k_norm<<<NROWS, 256>>>(nrm);
    k_pos<<<512, 256>>>(nrm, pos);
    k_sim<<<NT * (NT + 1) / 2, 256>>>(nrm, part);   // 2080 blocks
    k_neg<<<NROWS / 256, 256>>>(part, neg);
    k_loss<<<1, 256>>>(neg, pos, out);
}